// round 15
// baseline (speedup 1.0000x reference)
#include <cuda_runtime.h>
#include <cuda_bf16.h>
#include <math.h>
#include <stdint.h>

#define BATCH 16
#define CCH   512
#define NTOK  3136
#define MTOT  (BATCH*NTOK)     // 50176
#define NBLK64 (MTOT/64)       // 784
#define L2EPS 1e-12f

// ---------------- scratch (device globals; no runtime allocation) ------------
__device__ __nv_bfloat16 gx_hi[(size_t)MTOT * 512];  // xt split
__device__ __nv_bfloat16 gx_lo[(size_t)MTOT * 512];
__device__ __nv_bfloat16 gq_hi[(size_t)MTOT * 512];  // PRE-norm Q split
__device__ __nv_bfloat16 gq_lo[(size_t)MTOT * 512];
__device__ __nv_bfloat16 gk_hi[(size_t)MTOT * 512];  // PRE-norm K split
__device__ __nv_bfloat16 gk_lo[(size_t)MTOT * 512];
__device__ __nv_bfloat16 gw_hi[1792 * 512];          // W^T rows: wq 0..511, wk 512..1023, wd1 1024..1535, wf 1536..1791
__device__ __nv_bfloat16 gw_lo[1792 * 512];
__device__ float g_ssp[8 * (size_t)MTOT];            // per-128col-block sumsq partials (Q:0..3, K:4..7)
__device__ float g_wgp[4 * (size_t)MTOT];            // per-128col-block Qpre . w_g partials
__device__ float g_invq[MTOT];
__device__ float g_invk[MTOT];
__device__ float g_c[MTOT];                          // qg_m * inv_q_m (coeff over prenorm basis)
__device__ float g_Gpart[NBLK64 * 512];
__device__ float g_sspart[NBLK64];                   // per-block sum qg^2
__device__ float g_dynpart[4 * (size_t)MTOT];
__device__ float g_dyn[MTOT];
__device__ float g_w[MTOT];
__device__ float g_G[BATCH * 512];

__device__ __forceinline__ float gelu_f(float x) {
    return 0.5f * x * (1.0f + erff(x * 0.70710678118654752440f));
}

// ---------------- PTX helpers (baseline PTX only) ----------------------------
__device__ __forceinline__ uint32_t smem_u32(const void* p) {
    uint32_t a;
    asm("{ .reg .u64 t; cvta.to.shared.u64 t, %1; cvt.u32.u64 %0, t; }" : "=r"(a) : "l"(p));
    return a;
}
__device__ __forceinline__ void cpa16(uint32_t s, const void* g) {
    asm volatile("cp.async.cg.shared.global [%0], [%1], 16;" :: "r"(s), "l"(g));
}
__device__ __forceinline__ void ldsm4(uint32_t* r, uint32_t addr) {
    asm volatile("ldmatrix.sync.aligned.m8n8.x4.shared.b16 {%0,%1,%2,%3}, [%4];"
                 : "=r"(r[0]), "=r"(r[1]), "=r"(r[2]), "=r"(r[3]) : "r"(addr));
}
__device__ __forceinline__ void mma16816(float* d, const uint32_t* a, const uint32_t* b) {
    asm volatile(
        "mma.sync.aligned.m16n8k16.row.col.f32.bf16.bf16.f32 "
        "{%0,%1,%2,%3}, {%4,%5,%6,%7}, {%8,%9}, {%0,%1,%2,%3};"
        : "+f"(d[0]), "+f"(d[1]), "+f"(d[2]), "+f"(d[3])
        : "r"(a[0]), "r"(a[1]), "r"(a[2]), "r"(a[3]), "r"(b[0]), "r"(b[1]));
}
__device__ __forceinline__ void split_bf16(float x, __nv_bfloat16& h, __nv_bfloat16& l) {
    h = __float2bfloat16(x);
    l = __float2bfloat16(x - __bfloat162float(h));
}

// ---------------- weights: transpose to [N][K] rows + split ------------------
__global__ __launch_bounds__(256) void k_prep_w(
    const float* __restrict__ wq, const float* __restrict__ wk,
    const float* __restrict__ wd1, const float* __restrict__ wf)
{
    __shared__ float sm[32][33];
    const int tx = threadIdx.x, ty = threadIdx.y;
    const float* W; int N, r0;
    switch (blockIdx.z) {
        case 0: W = wq;  N = 512; r0 = 0;    break;
        case 1: W = wk;  N = 512; r0 = 512;  break;
        case 2: W = wd1; N = 512; r0 = 1024; break;
        default: W = wf; N = 256; r0 = 1536; break;
    }
    const int k0 = blockIdx.x * 32, n0 = blockIdx.y * 32;
    if (n0 >= N) return;
#pragma unroll
    for (int i = 0; i < 4; i++)
        sm[ty + 8 * i][tx] = W[(size_t)(k0 + ty + 8 * i) * N + n0 + tx];
    __syncthreads();
#pragma unroll
    for (int i = 0; i < 4; i++) {
        int n = n0 + ty + 8 * i;
        float v = sm[tx][ty + 8 * i];
        size_t o = (size_t)(r0 + n) * 512 + k0 + tx;
        __nv_bfloat16 h, l; split_bf16(v, h, l);
        gw_hi[o] = h; gw_lo[o] = l;
    }
}

// ---------------- transpose + split x -> xt hi/lo [M,512] --------------------
__global__ __launch_bounds__(256) void k_prep_x(const float* __restrict__ x)
{
    __shared__ float sm[32][33];
    const int tx = threadIdx.x, ty = threadIdx.y;
    const int b = blockIdx.z, c0 = blockIdx.y * 32, n0 = blockIdx.x * 32;
    const float* xb = x + ((size_t)b * CCH + c0) * NTOK + n0;
#pragma unroll
    for (int i = 0; i < 4; i++)
        sm[ty + 8 * i][tx] = xb[(size_t)(ty + 8 * i) * NTOK + tx];
    __syncthreads();
#pragma unroll
    for (int i = 0; i < 4; i++) {
        int r = ty + 8 * i;
        float v = sm[tx][r];
        size_t o = (size_t)(b * NTOK + n0 + r) * 512 + c0 + tx;
        __nv_bfloat16 h, l; split_bf16(v, h, l);
        gx_hi[o] = h; gx_lo[o] = l;
    }
}

// ---------------- mma.sync split-bf16 GEMM (CTA tile 128x128, K=512) ---------
// MODE 0: QK  (A=gx,  B rows bx*128 in 0..1023;  epi: +bias -> prenorm splits + ss/wg partials)
// MODE 1: DYN (A=gq prenorm, B rows 1024+bx*128; epi: inv_q scale, gelu(+bd1)*wd2 rowsum -> g_dynpart)
// MODE 2: OUT (A computed in-kernel: gelu(w*G*Knorm+Qnorm); B rows 1536+bx*128; epi: +bf -> transposed out)
#define APITCH 80            // bytes per smem row (32 bf16 + 16B pad): ldmatrix conflict-free
#define STG_BYTES 40960      // 4 matrices * 128 rows * 80B
#define SMEM_SZ (2 * STG_BYTES)
#define SMEM_SZ_OUT (2 * STG_BYTES + 8192)

template <int MODE>
__global__ __launch_bounds__(256, 1) void k_gemm_mma(
    const float* __restrict__ p0, const float* __restrict__ p1,
    const float* __restrict__ p2, float* __restrict__ outp)
{
    extern __shared__ char smem[];
    const uint32_t sb = smem_u32(smem);
    const int tid  = threadIdx.x;
    const int lane = tid & 31;
    const int wid  = tid >> 5;
    const int wm   = wid >> 2;   // 0..1 -> 64 rows each
    const int wn   = wid & 3;    // 0..3 -> 32 cols each
    const int m0   = blockIdx.y * 128;
    const int bx   = blockIdx.x;
    const int brow = (MODE == 0 ? 0 : (MODE == 1 ? 1024 : 1536)) + bx * 128;

    const __nv_bfloat16* a_hi = (MODE == 1) ? gq_hi : gx_hi;
    const __nv_bfloat16* a_lo = (MODE == 1) ? gq_lo : gx_lo;

    // MODE 2 extras
    float* GsA = (float*)(smem + 2 * STG_BYTES);
    float* GsB = GsA + 512;
    float* w_s = GsB + 512;
    float* iq_s = w_s + 128;
    float* ik_s = iq_s + 128;
    uint32_t* bfl = (uint32_t*)(ik_s + 128);
    int bA = 0;
    if (MODE == 2) {
        bA = m0 / NTOK;
        int bB = (bA == BATCH - 1) ? bA : bA + 1;
        for (int i = tid; i < 512; i += 256) {
            GsA[i] = g_G[bA * 512 + i];
            GsB[i] = g_G[bB * 512 + i];
        }
        if (tid < 128) {
            int m = m0 + tid;
            w_s[tid]  = g_w[m];
            iq_s[tid] = g_invq[m];
            ik_s[tid] = g_invk[m];
            bfl[tid]  = (m / NTOK != bA) ? 1u : 0u;
        }
        __syncthreads();
    }

    const uint32_t aOff = (uint32_t)((wm * 64 + (lane & 15)) * APITCH + (lane >> 4) * 16);
    const uint32_t bOff = (uint32_t)((wn * 32 + (lane & 7) + ((lane >> 4) << 3)) * APITCH
                                     + ((lane >> 3) & 1) * 16);

    float acc[4][4][4];
#pragma unroll
    for (int mt = 0; mt < 4; mt++)
#pragma unroll
        for (int nt = 0; nt < 4; nt++)
#pragma unroll
            for (int k = 0; k < 4; k++) acc[mt][nt][k] = 0.f;

    auto loadChunk = [&](int c, int s) {
        const int kt = c * 32;
        const uint32_t base = sb + s * STG_BYTES;
#pragma unroll
        for (int i = 0; i < 2; i++) {
            int e = tid + 256 * i;
            int row = e >> 2, seg = e & 3;
            uint32_t d = base + (uint32_t)(row * APITCH + seg * 16);
            size_t gb = (size_t)(brow + row) * 512 + kt + seg * 8;
            if (MODE != 2) {
                size_t ga = (size_t)(m0 + row) * 512 + kt + seg * 8;
                cpa16(d,         a_hi + ga);
                cpa16(d + 10240, a_lo + ga);
            }
            cpa16(d + 20480, gw_hi + gb);
            cpa16(d + 30720, gw_lo + gb);
        }
        asm volatile("cp.async.commit_group;" ::: "memory");
    };

    auto computeAct = [&](int c, int s) {
        const int kt = c * 32;
        char* stage = smem + s * STG_BYTES;
#pragma unroll
        for (int i = 0; i < 2; i++) {
            int u = tid + 256 * i;
            int row = u >> 2, seg = u & 3;
            size_t gb = (size_t)(m0 + row) * 512 + kt + seg * 8;
            uint4 qh4 = *(const uint4*)(gq_hi + gb);
            uint4 ql4 = *(const uint4*)(gq_lo + gb);
            uint4 kh4 = *(const uint4*)(gk_hi + gb);
            uint4 kl4 = *(const uint4*)(gk_lo + gb);
            const __nv_bfloat16* qh = (const __nv_bfloat16*)&qh4;
            const __nv_bfloat16* ql = (const __nv_bfloat16*)&ql4;
            const __nv_bfloat16* kh = (const __nv_bfloat16*)&kh4;
            const __nv_bfloat16* kl = (const __nv_bfloat16*)&kl4;
            float iq = iq_s[row], ik = ik_s[row], wm2 = w_s[row];
            const float* Gp = bfl[row] ? GsB : GsA;
            __align__(16) __nv_bfloat16 hh[8];
            __align__(16) __nv_bfloat16 ll[8];
#pragma unroll
            for (int j = 0; j < 8; j++) {
                float q  = iq * (__bfloat162float(qh[j]) + __bfloat162float(ql[j]));
                float kv = ik * (__bfloat162float(kh[j]) + __bfloat162float(kl[j]));
                float a = gelu_f(wm2 * Gp[kt + seg * 8 + j] * kv + q);
                split_bf16(a, hh[j], ll[j]);
            }
            char* d = stage + row * APITCH + seg * 16;
            *(uint4*)d = *(uint4*)hh;
            *(uint4*)(d + 10240) = *(uint4*)ll;
        }
    };

    loadChunk(0, 0);
    for (int c = 0; c < 16; c++) {
        asm volatile("cp.async.wait_group 0;" ::: "memory");
        __syncthreads();
        if (c < 15) loadChunk(c + 1, (c + 1) & 1);
        if (MODE == 2) {
            computeAct(c, c & 1);
            __syncthreads();
        }
        const uint32_t base = sb + (c & 1) * STG_BYTES;
#pragma unroll
        for (int ks = 0; ks < 2; ks++) {
            uint32_t ah[4][4], al[4][4], bh[8], bl[8];
            const uint32_t aB = base + aOff + ks * 32;
#pragma unroll
            for (int mt = 0; mt < 4; mt++) {
                ldsm4(ah[mt], aB + mt * 16 * APITCH);
                ldsm4(al[mt], aB + 10240 + mt * 16 * APITCH);
            }
            const uint32_t bB = base + 20480 + bOff + ks * 32;
#pragma unroll
            for (int p = 0; p < 2; p++) {
                ldsm4(&bh[4 * p], bB + p * 16 * APITCH);
                ldsm4(&bl[4 * p], bB + 10240 + p * 16 * APITCH);
            }
#pragma unroll
            for (int mt = 0; mt < 4; mt++)
#pragma unroll
                for (int nt = 0; nt < 4; nt++) {
                    mma16816(acc[mt][nt], ah[mt], &bh[2 * nt]);
                    mma16816(acc[mt][nt], ah[mt], &bl[2 * nt]);
                    mma16816(acc[mt][nt], al[mt], &bh[2 * nt]);
                }
        }
        __syncthreads();
    }

    // ---- epilogue ----
    const int r0w = wm * 64 + (lane >> 2);
    const int c0w = wn * 32 + (lane & 3) * 2;

    if (MODE == 0) {
        float* sf = (float*)smem;
#pragma unroll
        for (int mt = 0; mt < 4; mt++)
#pragma unroll
            for (int nt = 0; nt < 4; nt++)
#pragma unroll
                for (int k = 0; k < 4; k++) {
                    int r  = r0w + mt * 16 + ((k >> 1) << 3);
                    int cc = c0w + nt * 8 + (k & 1);
                    sf[r * 132 + cc] = acc[mt][nt][k];
                }
        __syncthreads();
        for (int r = wid; r < 128; r += 8) {
            int c4 = lane * 4;
            float4 v = *(float4*)&sf[r * 132 + c4];
            int jg = bx * 128 + c4;
            if (jg < 512) {
                v.x += __ldg(p0 + jg); v.y += __ldg(p0 + jg + 1);
                v.z += __ldg(p0 + jg + 2); v.w += __ldg(p0 + jg + 3);
            } else {
                int j2 = jg - 512;
                v.x += __ldg(p1 + j2); v.y += __ldg(p1 + j2 + 1);
                v.z += __ldg(p1 + j2 + 2); v.w += __ldg(p1 + j2 + 3);
            }
            int m = m0 + r;
            // partial sum of squares over this 128-col block
            float ssp = v.x * v.x + v.y * v.y + v.z * v.z + v.w * v.w;
            float wgp = 0.f;
            if (bx < 4) {
                wgp = v.x * __ldg(p2 + jg) + v.y * __ldg(p2 + jg + 1)
                    + v.z * __ldg(p2 + jg + 2) + v.w * __ldg(p2 + jg + 3);
            }
#pragma unroll
            for (int o = 16; o > 0; o >>= 1) {
                ssp += __shfl_xor_sync(0xffffffff, ssp, o);
                wgp += __shfl_xor_sync(0xffffffff, wgp, o);
            }
            if (lane == 0) {
                g_ssp[(size_t)bx * MTOT + m] = ssp;
                if (bx < 4) g_wgp[(size_t)bx * MTOT + m] = wgp;
            }
            // split + store prenorm bf16
            __align__(8) __nv_bfloat16 hh[4];
            __align__(8) __nv_bfloat16 ll[4];
            split_bf16(v.x, hh[0], ll[0]); split_bf16(v.y, hh[1], ll[1]);
            split_bf16(v.z, hh[2], ll[2]); split_bf16(v.w, hh[3], ll[3]);
            __nv_bfloat16 *dh, *dl; int jloc;
            if (bx < 4) { dh = gq_hi; dl = gq_lo; jloc = bx * 128 + c4; }
            else        { dh = gk_hi; dl = gk_lo; jloc = (bx - 4) * 128 + c4; }
            *(uint2*)(dh + (size_t)m * 512 + jloc) = *(uint2*)hh;
            *(uint2*)(dl + (size_t)m * 512 + jloc) = *(uint2*)ll;
        }
    } else if (MODE == 1) {
        float* sred = (float*)smem;          // [4][128]
        const int cbase = bx * 128 + c0w;
#pragma unroll
        for (int mt = 0; mt < 4; mt++) {
            float iq0 = __ldg(g_invq + m0 + r0w + mt * 16);
            float iq1 = __ldg(g_invq + m0 + r0w + mt * 16 + 8);
            float sA = 0.f, sB = 0.f;
#pragma unroll
            for (int nt = 0; nt < 4; nt++)
#pragma unroll
                for (int k = 0; k < 4; k++) {
                    int col = cbase + nt * 8 + (k & 1);
                    float iq = (k < 2) ? iq0 : iq1;
                    float z = iq * acc[mt][nt][k] + __ldg(p0 + col);
                    float v = gelu_f(z) * __ldg(p1 + col);
                    if (k < 2) sA += v; else sB += v;
                }
            sA += __shfl_xor_sync(0xffffffff, sA, 1);
            sA += __shfl_xor_sync(0xffffffff, sA, 2);
            sB += __shfl_xor_sync(0xffffffff, sB, 1);
            sB += __shfl_xor_sync(0xffffffff, sB, 2);
            if ((lane & 3) == 0) {
                int r = r0w + mt * 16;
                sred[wn * 128 + r]     = sA;
                sred[wn * 128 + r + 8] = sB;
            }
        }
        __syncthreads();
        if (tid < 128) {
            float s = sred[tid] + sred[128 + tid] + sred[256 + tid] + sred[384 + tid];
            g_dynpart[(size_t)bx * MTOT + m0 + tid] = s;
        }
    } else {
        float* sf = (float*)smem;            // transposed: [ch][tok] pitch 132
#pragma unroll
        for (int mt = 0; mt < 4; mt++)
#pragma unroll
            for (int nt = 0; nt < 4; nt++)
#pragma unroll
                for (int k = 0; k < 4; k++) {
                    int r  = r0w + mt * 16 + ((k >> 1) << 3);
                    int cc = c0w + nt * 8 + (k & 1);
                    sf[cc * 132 + r] = acc[mt][nt][k];
                }
        __syncthreads();
        for (int ch = wid; ch < 128; ch += 8) {
            int t4 = lane * 4;
            float4 v = *(float4*)&sf[ch * 132 + t4];
            int chg = bx * 128 + ch;
            float bias = __ldg(p0 + chg);
            v.x += bias; v.y += bias; v.z += bias; v.w += bias;
            int m = m0 + t4;
            int b = m / NTOK;
            int n = m - b * NTOK;
            *(float4*)&outp[((size_t)b * 256 + chg) * NTOK + n] = v;
        }
    }
}

// ---------------- per-token scalars: inv_q, inv_k, c; qg^2 partials ----------
__global__ __launch_bounds__(64) void k_scalar()
{
    __shared__ float s2[2];
    const int m = blockIdx.x * 64 + threadIdx.x;
    const int lane = threadIdx.x & 31;
    const int warp = threadIdx.x >> 5;
    float ssq = 0.f, ssk = 0.f, wgd = 0.f;
#pragma unroll
    for (int i = 0; i < 4; i++) {
        ssq += g_ssp[(size_t)i * MTOT + m];
        ssk += g_ssp[(size_t)(4 + i) * MTOT + m];
        wgd += g_wgp[(size_t)i * MTOT + m];
    }
    float invq = 1.f / fmaxf(sqrtf(ssq), L2EPS);
    float invk = 1.f / fmaxf(sqrtf(ssk), L2EPS);
    float qg = invq * wgd;
    g_invq[m] = invq;
    g_invk[m] = invk;
    g_c[m] = invq * qg;
    float s = qg * qg;
#pragma unroll
    for (int o = 16; o > 0; o >>= 1) s += __shfl_xor_sync(0xffffffff, s, o);
    if (lane == 0) s2[warp] = s;
    __syncthreads();
    if (threadIdx.x == 0) g_sspart[blockIdx.x] = s2[0] + s2[1];
}

// ---------------- G partials: Gpart[blk] = sum_m c_m * Qpre_m ----------------
__global__ __launch_bounds__(256) void k_gpart()
{
    __shared__ float sG[8][512];
    const int tid  = threadIdx.x;
    const int lane = tid & 31;
    const int warp = tid >> 5;
    const int m0 = blockIdx.x * 64;

    float Gl[16];
#pragma unroll
    for (int u = 0; u < 16; u++) Gl[u] = 0.f;

    for (int t = warp; t < 64; t += 8) {
        const int m = m0 + t;
        const float cm = g_c[m];
        size_t base = (size_t)m * 512 + lane * 16;
        uint4 a0 = *(const uint4*)(gq_hi + base);
        uint4 a1 = *(const uint4*)(gq_hi + base + 8);
        uint4 b0 = *(const uint4*)(gq_lo + base);
        uint4 b1 = *(const uint4*)(gq_lo + base + 8);
        const __nv_bfloat16* h0 = (const __nv_bfloat16*)&a0;
        const __nv_bfloat16* h1 = (const __nv_bfloat16*)&a1;
        const __nv_bfloat16* l0 = (const __nv_bfloat16*)&b0;
        const __nv_bfloat16* l1 = (const __nv_bfloat16*)&b1;
#pragma unroll
        for (int j = 0; j < 8; j++) {
            Gl[j]     += cm * (__bfloat162float(h0[j]) + __bfloat162float(l0[j]));
            Gl[8 + j] += cm * (__bfloat162float(h1[j]) + __bfloat162float(l1[j]));
        }
    }
#pragma unroll
    for (int j = 0; j < 16; j++) sG[warp][lane * 16 + j] = Gl[j];
    __syncthreads();
    for (int j = tid; j < 512; j += 256) {
        float s = 0.f;
#pragma unroll
        for (int w2 = 0; w2 < 8; w2++) s += sG[w2][j];
        g_Gpart[blockIdx.x * 512 + j] = s;
    }
}

// ---------------- per-batch finalize: G, dyn assembly, softmax ---------------
__global__ __launch_bounds__(256) void k_finalize(const float* __restrict__ bd2)
{
    __shared__ float red[256];
    const int b   = blockIdx.x;
    const int tid = threadIdx.x;
    const float bd2v = bd2[0];

    if (tid == 0) {
        float s = 0.f;
        for (int i = 0; i < 49; i++) s += g_sspart[b * 49 + i];
        red[0] = s;
    }
    __syncthreads();
    const float SCALE = 0.0625f;      // 256^-0.5
    float denom = fmaxf(SCALE * sqrtf(red[0]), L2EPS);
    float f = SCALE / denom;
    __syncthreads();

    for (int j = tid; j < 512; j += 256) {
        float s = 0.f;
        for (int i = 0; i < 49; i++) s += g_Gpart[(size_t)(b * 49 + i) * 512 + j];
        g_G[b * 512 + j] = f * s;
    }

    float mx = -1e30f;
    for (int n = tid; n < NTOK; n += 256) {
        size_t idx = (size_t)b * NTOK + n;
        float v = g_dynpart[idx] + g_dynpart[(size_t)MTOT + idx]
                + g_dynpart[2 * (size_t)MTOT + idx] + g_dynpart[3 * (size_t)MTOT + idx] + bd2v;
        g_dyn[idx] = v;
        mx = fmaxf(mx, v);
    }
    red[tid] = mx; __syncthreads();
    for (int o = 128; o > 0; o >>= 1) { if (tid < o) red[tid] = fmaxf(red[tid], red[tid + o]); __syncthreads(); }
    mx = red[0]; __syncthreads();

    float se = 0.f;
    for (int n = tid; n < NTOK; n += 256) se += expf(g_dyn[b * NTOK + n] - mx);
    red[tid] = se; __syncthreads();
    for (int o = 128; o > 0; o >>= 1) { if (tid < o) red[tid] += red[tid + o]; __syncthreads(); }
    float inv = 1.f / red[0];
    for (int n = tid; n < NTOK; n += 256)
        g_w[b * NTOK + n] = expf(g_dyn[b * NTOK + n] - mx) * inv;
}

// -----------------------------------------------------------------------------
extern "C" void kernel_launch(void* const* d_in, const int* in_sizes, int n_in,
                              void* d_out, int out_size)
{
    const float* x   = (const float*)d_in[0];
    const float* wq  = (const float*)d_in[1];
    const float* bq  = (const float*)d_in[2];
    const float* wk  = (const float*)d_in[3];
    const float* bk  = (const float*)d_in[4];
    const float* w_g = (const float*)d_in[5];
    const float* wd1 = (const float*)d_in[6];
    const float* bd1 = (const float*)d_in[7];
    const float* wd2 = (const float*)d_in[8];
    const float* bd2 = (const float*)d_in[9];
    const float* wf  = (const float*)d_in[10];
    const float* bf  = (const float*)d_in[11];
    float* out = (float*)d_out;

    cudaFuncSetAttribute(k_gemm_mma<0>, cudaFuncAttributeMaxDynamicSharedMemorySize, SMEM_SZ);
    cudaFuncSetAttribute(k_gemm_mma<1>, cudaFuncAttributeMaxDynamicSharedMemorySize, SMEM_SZ);
    cudaFuncSetAttribute(k_gemm_mma<2>, cudaFuncAttributeMaxDynamicSharedMemorySize, SMEM_SZ_OUT);

    k_prep_w<<<dim3(16, 16, 4), dim3(32, 8)>>>(wq, wk, wd1, wf);
    k_prep_x<<<dim3(98, 16, 16), dim3(32, 8)>>>(x);
    k_gemm_mma<0><<<dim3(8, MTOT / 128), 256, SMEM_SZ>>>(bq, bk, w_g, nullptr);
    k_scalar<<<NBLK64, 64>>>();
    k_gpart<<<NBLK64, 256>>>();
    k_gemm_mma<1><<<dim3(4, MTOT / 128), 256, SMEM_SZ>>>(bd1, wd2, nullptr, nullptr);
    k_finalize<<<BATCH, 256>>>(bd2);
    k_gemm_mma<2><<<dim3(2, MTOT / 128), 256, SMEM_SZ_OUT>>>(bf, nullptr, nullptr, out);
}

// round 16
// speedup vs baseline: 1.0044x; 1.0044x over previous
#include <cuda_runtime.h>
#include <cuda_bf16.h>
#include <math.h>
#include <stdint.h>

#define BATCH 16
#define CCH   512
#define NTOK  3136
#define MTOT  (BATCH*NTOK)     // 50176
#define NBLK64 (MTOT/64)       // 784
#define L2EPS 1e-12f

// ---------------- scratch (device globals; no runtime allocation) ------------
__device__ __nv_bfloat16 gx_hi[(size_t)MTOT * 512];  // xt split
__device__ __nv_bfloat16 gx_lo[(size_t)MTOT * 512];
__device__ __nv_bfloat16 gq_hi[(size_t)MTOT * 512];  // PRE-norm Q split
__device__ __nv_bfloat16 gq_lo[(size_t)MTOT * 512];
__device__ __nv_bfloat16 gk_hi[(size_t)MTOT * 512];  // PRE-norm K split
__device__ __nv_bfloat16 gk_lo[(size_t)MTOT * 512];
__device__ __nv_bfloat16 gw_hi[1792 * 512];          // W^T rows: wq 0..511, wk 512..1023, wd1 1024..1535, wf 1536..1791
__device__ __nv_bfloat16 gw_lo[1792 * 512];
__device__ float g_ssp[8 * (size_t)MTOT];            // per-128col-block sumsq partials (Q:0..3, K:4..7)
__device__ float g_wgp[4 * (size_t)MTOT];            // per-128col-block Qpre . w_g partials
__device__ float g_invq[MTOT];
__device__ float g_invk[MTOT];
__device__ float g_c[MTOT];                          // qg_m * inv_q_m (coeff over prenorm basis)
__device__ float g_Gpart[NBLK64 * 512];
__device__ float g_sspart[NBLK64];                   // per-block sum qg^2
__device__ float g_dynpart[4 * (size_t)MTOT];
__device__ float g_dyn[MTOT];
__device__ float g_w[MTOT];
__device__ float g_G[BATCH * 512];

__device__ __forceinline__ float gelu_f(float x) {
    return 0.5f * x * (1.0f + erff(x * 0.70710678118654752440f));
}

// ---------------- PTX helpers (baseline PTX only) ----------------------------
__device__ __forceinline__ uint32_t smem_u32(const void* p) {
    uint32_t a;
    asm("{ .reg .u64 t; cvta.to.shared.u64 t, %1; cvt.u32.u64 %0, t; }" : "=r"(a) : "l"(p));
    return a;
}
__device__ __forceinline__ void cpa16(uint32_t s, const void* g) {
    asm volatile("cp.async.cg.shared.global [%0], [%1], 16;" :: "r"(s), "l"(g));
}
__device__ __forceinline__ void ldsm4(uint32_t* r, uint32_t addr) {
    asm volatile("ldmatrix.sync.aligned.m8n8.x4.shared.b16 {%0,%1,%2,%3}, [%4];"
                 : "=r"(r[0]), "=r"(r[1]), "=r"(r[2]), "=r"(r[3]) : "r"(addr));
}
__device__ __forceinline__ void mma16816(float* d, const uint32_t* a, const uint32_t* b) {
    asm volatile(
        "mma.sync.aligned.m16n8k16.row.col.f32.bf16.bf16.f32 "
        "{%0,%1,%2,%3}, {%4,%5,%6,%7}, {%8,%9}, {%0,%1,%2,%3};"
        : "+f"(d[0]), "+f"(d[1]), "+f"(d[2]), "+f"(d[3])
        : "r"(a[0]), "r"(a[1]), "r"(a[2]), "r"(a[3]), "r"(b[0]), "r"(b[1]));
}
__device__ __forceinline__ void split_bf16(float x, __nv_bfloat16& h, __nv_bfloat16& l) {
    h = __float2bfloat16(x);
    l = __float2bfloat16(x - __bfloat162float(h));
}

// ---------------- weights: transpose to [N][K] rows + split ------------------
__global__ __launch_bounds__(256) void k_prep_w(
    const float* __restrict__ wq, const float* __restrict__ wk,
    const float* __restrict__ wd1, const float* __restrict__ wf)
{
    __shared__ float sm[32][33];
    const int tx = threadIdx.x, ty = threadIdx.y;
    const float* W; int N, r0;
    switch (blockIdx.z) {
        case 0: W = wq;  N = 512; r0 = 0;    break;
        case 1: W = wk;  N = 512; r0 = 512;  break;
        case 2: W = wd1; N = 512; r0 = 1024; break;
        default: W = wf; N = 256; r0 = 1536; break;
    }
    const int k0 = blockIdx.x * 32, n0 = blockIdx.y * 32;
    if (n0 >= N) return;
#pragma unroll
    for (int i = 0; i < 4; i++)
        sm[ty + 8 * i][tx] = W[(size_t)(k0 + ty + 8 * i) * N + n0 + tx];
    __syncthreads();
#pragma unroll
    for (int i = 0; i < 4; i++) {
        int n = n0 + ty + 8 * i;
        float v = sm[tx][ty + 8 * i];
        size_t o = (size_t)(r0 + n) * 512 + k0 + tx;
        __nv_bfloat16 h, l; split_bf16(v, h, l);
        gw_hi[o] = h; gw_lo[o] = l;
    }
}

// ---------------- transpose + split x -> xt hi/lo [M,512] --------------------
__global__ __launch_bounds__(256) void k_prep_x(const float* __restrict__ x)
{
    __shared__ float sm[32][33];
    const int tx = threadIdx.x, ty = threadIdx.y;
    const int b = blockIdx.z, c0 = blockIdx.y * 32, n0 = blockIdx.x * 32;
    const float* xb = x + ((size_t)b * CCH + c0) * NTOK + n0;
#pragma unroll
    for (int i = 0; i < 4; i++)
        sm[ty + 8 * i][tx] = xb[(size_t)(ty + 8 * i) * NTOK + tx];
    __syncthreads();
#pragma unroll
    for (int i = 0; i < 4; i++) {
        int r = ty + 8 * i;
        float v = sm[tx][r];
        size_t o = (size_t)(b * NTOK + n0 + r) * 512 + c0 + tx;
        __nv_bfloat16 h, l; split_bf16(v, h, l);
        gx_hi[o] = h; gx_lo[o] = l;
    }
}

// ---------------- mma.sync split-bf16 GEMM (CTA tile 128x128, K=512) ---------
// MODE 0: QK  (A=gx,  B rows bx*128 in 0..1023;  epi: +bias -> prenorm splits + ss/wg partials)
// MODE 1: DYN (A=gq prenorm, B rows 1024+bx*128; epi: inv_q scale, gelu(+bd1)*wd2 rowsum -> g_dynpart)
// MODE 2: OUT (A computed in-kernel: gelu(w*G*Knorm+Qnorm); B rows 1536+bx*128; epi: +bf -> transposed out)
#define APITCH 80            // bytes per smem row (32 bf16 + 16B pad): ldmatrix conflict-free
#define STG_BYTES 40960      // 4 matrices * 128 rows * 80B
#define SMEM_SZ (2 * STG_BYTES)
#define SMEM_SZ_OUT (2 * STG_BYTES + 8192)

template <int MODE>
__global__ __launch_bounds__(256, 1) void k_gemm_mma(
    const float* __restrict__ p0, const float* __restrict__ p1,
    const float* __restrict__ p2, float* __restrict__ outp)
{
    extern __shared__ char smem[];
    const uint32_t sb = smem_u32(smem);
    const int tid  = threadIdx.x;
    const int lane = tid & 31;
    const int wid  = tid >> 5;
    const int wm   = wid >> 2;   // 0..1 -> 64 rows each
    const int wn   = wid & 3;    // 0..3 -> 32 cols each
    const int m0   = blockIdx.y * 128;
    const int bx   = blockIdx.x;
    const int brow = (MODE == 0 ? 0 : (MODE == 1 ? 1024 : 1536)) + bx * 128;

    const __nv_bfloat16* a_hi = (MODE == 1) ? gq_hi : gx_hi;
    const __nv_bfloat16* a_lo = (MODE == 1) ? gq_lo : gx_lo;

    // MODE 2 extras
    float* GsA = (float*)(smem + 2 * STG_BYTES);
    float* GsB = GsA + 512;
    float* w_s = GsB + 512;
    float* iq_s = w_s + 128;
    float* ik_s = iq_s + 128;
    uint32_t* bfl = (uint32_t*)(ik_s + 128);
    int bA = 0;
    if (MODE == 2) {
        bA = m0 / NTOK;
        int bB = (bA == BATCH - 1) ? bA : bA + 1;
        for (int i = tid; i < 512; i += 256) {
            GsA[i] = g_G[bA * 512 + i];
            GsB[i] = g_G[bB * 512 + i];
        }
        if (tid < 128) {
            int m = m0 + tid;
            w_s[tid]  = g_w[m];
            iq_s[tid] = g_invq[m];
            ik_s[tid] = g_invk[m];
            bfl[tid]  = (m / NTOK != bA) ? 1u : 0u;
        }
        __syncthreads();
    }

    const uint32_t aOff = (uint32_t)((wm * 64 + (lane & 15)) * APITCH + (lane >> 4) * 16);
    const uint32_t bOff = (uint32_t)((wn * 32 + (lane & 7) + ((lane >> 4) << 3)) * APITCH
                                     + ((lane >> 3) & 1) * 16);

    float acc[4][4][4];
#pragma unroll
    for (int mt = 0; mt < 4; mt++)
#pragma unroll
        for (int nt = 0; nt < 4; nt++)
#pragma unroll
            for (int k = 0; k < 4; k++) acc[mt][nt][k] = 0.f;

    auto loadChunk = [&](int c, int s) {
        const int kt = c * 32;
        const uint32_t base = sb + s * STG_BYTES;
#pragma unroll
        for (int i = 0; i < 2; i++) {
            int e = tid + 256 * i;
            int row = e >> 2, seg = e & 3;
            uint32_t d = base + (uint32_t)(row * APITCH + seg * 16);
            size_t gb = (size_t)(brow + row) * 512 + kt + seg * 8;
            if (MODE != 2) {
                size_t ga = (size_t)(m0 + row) * 512 + kt + seg * 8;
                cpa16(d,         a_hi + ga);
                cpa16(d + 10240, a_lo + ga);
            }
            cpa16(d + 20480, gw_hi + gb);
            cpa16(d + 30720, gw_lo + gb);
        }
        asm volatile("cp.async.commit_group;" ::: "memory");
    };

    auto computeAct = [&](int c, int s) {
        const int kt = c * 32;
        char* stage = smem + s * STG_BYTES;
#pragma unroll
        for (int i = 0; i < 2; i++) {
            int u = tid + 256 * i;
            int row = u >> 2, seg = u & 3;
            size_t gb = (size_t)(m0 + row) * 512 + kt + seg * 8;
            uint4 qh4 = *(const uint4*)(gq_hi + gb);
            uint4 ql4 = *(const uint4*)(gq_lo + gb);
            uint4 kh4 = *(const uint4*)(gk_hi + gb);
            uint4 kl4 = *(const uint4*)(gk_lo + gb);
            const __nv_bfloat16* qh = (const __nv_bfloat16*)&qh4;
            const __nv_bfloat16* ql = (const __nv_bfloat16*)&ql4;
            const __nv_bfloat16* kh = (const __nv_bfloat16*)&kh4;
            const __nv_bfloat16* kl = (const __nv_bfloat16*)&kl4;
            float iq = iq_s[row], ik = ik_s[row], wm2 = w_s[row];
            const float* Gp = bfl[row] ? GsB : GsA;
            __align__(16) __nv_bfloat16 hh[8];
            __align__(16) __nv_bfloat16 ll[8];
#pragma unroll
            for (int j = 0; j < 8; j++) {
                float q  = iq * (__bfloat162float(qh[j]) + __bfloat162float(ql[j]));
                float kv = ik * (__bfloat162float(kh[j]) + __bfloat162float(kl[j]));
                float a = gelu_f(wm2 * Gp[kt + seg * 8 + j] * kv + q);
                split_bf16(a, hh[j], ll[j]);
            }
            char* d = stage + row * APITCH + seg * 16;
            *(uint4*)d = *(uint4*)hh;
            *(uint4*)(d + 10240) = *(uint4*)ll;
        }
    };

    loadChunk(0, 0);
    for (int c = 0; c < 16; c++) {
        asm volatile("cp.async.wait_group 0;" ::: "memory");
        __syncthreads();
        if (c < 15) loadChunk(c + 1, (c + 1) & 1);
        if (MODE == 2) {
            computeAct(c, c & 1);
            __syncthreads();
        }
        const uint32_t base = sb + (c & 1) * STG_BYTES;
#pragma unroll
        for (int ks = 0; ks < 2; ks++) {
            uint32_t ah[4][4], al[4][4], bh[8], bl[8];
            const uint32_t aB = base + aOff + ks * 32;
#pragma unroll
            for (int mt = 0; mt < 4; mt++) {
                ldsm4(ah[mt], aB + mt * 16 * APITCH);
                ldsm4(al[mt], aB + 10240 + mt * 16 * APITCH);
            }
            const uint32_t bB = base + 20480 + bOff + ks * 32;
#pragma unroll
            for (int p = 0; p < 2; p++) {
                ldsm4(&bh[4 * p], bB + p * 16 * APITCH);
                ldsm4(&bl[4 * p], bB + 10240 + p * 16 * APITCH);
            }
#pragma unroll
            for (int mt = 0; mt < 4; mt++)
#pragma unroll
                for (int nt = 0; nt < 4; nt++) {
                    mma16816(acc[mt][nt], ah[mt], &bh[2 * nt]);
                    mma16816(acc[mt][nt], ah[mt], &bl[2 * nt]);
                    mma16816(acc[mt][nt], al[mt], &bh[2 * nt]);
                }
        }
        __syncthreads();
    }

    // ---- epilogue ----
    const int r0w = wm * 64 + (lane >> 2);
    const int c0w = wn * 32 + (lane & 3) * 2;

    if (MODE == 0) {
        float* sf = (float*)smem;
#pragma unroll
        for (int mt = 0; mt < 4; mt++)
#pragma unroll
            for (int nt = 0; nt < 4; nt++)
#pragma unroll
                for (int k = 0; k < 4; k++) {
                    int r  = r0w + mt * 16 + ((k >> 1) << 3);
                    int cc = c0w + nt * 8 + (k & 1);
                    sf[r * 132 + cc] = acc[mt][nt][k];
                }
        __syncthreads();
        for (int r = wid; r < 128; r += 8) {
            int c4 = lane * 4;
            float4 v = *(float4*)&sf[r * 132 + c4];
            int jg = bx * 128 + c4;
            if (jg < 512) {
                v.x += __ldg(p0 + jg); v.y += __ldg(p0 + jg + 1);
                v.z += __ldg(p0 + jg + 2); v.w += __ldg(p0 + jg + 3);
            } else {
                int j2 = jg - 512;
                v.x += __ldg(p1 + j2); v.y += __ldg(p1 + j2 + 1);
                v.z += __ldg(p1 + j2 + 2); v.w += __ldg(p1 + j2 + 3);
            }
            int m = m0 + r;
            // partial sum of squares over this 128-col block
            float ssp = v.x * v.x + v.y * v.y + v.z * v.z + v.w * v.w;
            float wgp = 0.f;
            if (bx < 4) {
                wgp = v.x * __ldg(p2 + jg) + v.y * __ldg(p2 + jg + 1)
                    + v.z * __ldg(p2 + jg + 2) + v.w * __ldg(p2 + jg + 3);
            }
#pragma unroll
            for (int o = 16; o > 0; o >>= 1) {
                ssp += __shfl_xor_sync(0xffffffff, ssp, o);
                wgp += __shfl_xor_sync(0xffffffff, wgp, o);
            }
            if (lane == 0) {
                g_ssp[(size_t)bx * MTOT + m] = ssp;
                if (bx < 4) g_wgp[(size_t)bx * MTOT + m] = wgp;
            }
            // split + store prenorm bf16
            __align__(8) __nv_bfloat16 hh[4];
            __align__(8) __nv_bfloat16 ll[4];
            split_bf16(v.x, hh[0], ll[0]); split_bf16(v.y, hh[1], ll[1]);
            split_bf16(v.z, hh[2], ll[2]); split_bf16(v.w, hh[3], ll[3]);
            __nv_bfloat16 *dh, *dl; int jloc;
            if (bx < 4) { dh = gq_hi; dl = gq_lo; jloc = bx * 128 + c4; }
            else        { dh = gk_hi; dl = gk_lo; jloc = (bx - 4) * 128 + c4; }
            *(uint2*)(dh + (size_t)m * 512 + jloc) = *(uint2*)hh;
            *(uint2*)(dl + (size_t)m * 512 + jloc) = *(uint2*)ll;
        }
    } else if (MODE == 1) {
        float* sred = (float*)smem;          // [4][128]
        const int cbase = bx * 128 + c0w;
#pragma unroll
        for (int mt = 0; mt < 4; mt++) {
            float iq0 = __ldg(g_invq + m0 + r0w + mt * 16);
            float iq1 = __ldg(g_invq + m0 + r0w + mt * 16 + 8);
            float sA = 0.f, sB = 0.f;
#pragma unroll
            for (int nt = 0; nt < 4; nt++)
#pragma unroll
                for (int k = 0; k < 4; k++) {
                    int col = cbase + nt * 8 + (k & 1);
                    float iq = (k < 2) ? iq0 : iq1;
                    float z = iq * acc[mt][nt][k] + __ldg(p0 + col);
                    float v = gelu_f(z) * __ldg(p1 + col);
                    if (k < 2) sA += v; else sB += v;
                }
            sA += __shfl_xor_sync(0xffffffff, sA, 1);
            sA += __shfl_xor_sync(0xffffffff, sA, 2);
            sB += __shfl_xor_sync(0xffffffff, sB, 1);
            sB += __shfl_xor_sync(0xffffffff, sB, 2);
            if ((lane & 3) == 0) {
                int r = r0w + mt * 16;
                sred[wn * 128 + r]     = sA;
                sred[wn * 128 + r + 8] = sB;
            }
        }
        __syncthreads();
        if (tid < 128) {
            float s = sred[tid] + sred[128 + tid] + sred[256 + tid] + sred[384 + tid];
            g_dynpart[(size_t)bx * MTOT + m0 + tid] = s;
        }
    } else {
        float* sf = (float*)smem;            // transposed: [ch][tok] pitch 132
#pragma unroll
        for (int mt = 0; mt < 4; mt++)
#pragma unroll
            for (int nt = 0; nt < 4; nt++)
#pragma unroll
                for (int k = 0; k < 4; k++) {
                    int r  = r0w + mt * 16 + ((k >> 1) << 3);
                    int cc = c0w + nt * 8 + (k & 1);
                    sf[cc * 132 + r] = acc[mt][nt][k];
                }
        __syncthreads();
        for (int ch = wid; ch < 128; ch += 8) {
            int t4 = lane * 4;
            float4 v = *(float4*)&sf[ch * 132 + t4];
            int chg = bx * 128 + ch;
            float bias = __ldg(p0 + chg);
            v.x += bias; v.y += bias; v.z += bias; v.w += bias;
            int m = m0 + t4;
            int b = m / NTOK;
            int n = m - b * NTOK;
            *(float4*)&outp[((size_t)b * 256 + chg) * NTOK + n] = v;
        }
    }
}

// ---------------- per-token scalars: inv_q, inv_k, c; qg^2 partials ----------
__global__ __launch_bounds__(64) void k_scalar()
{
    __shared__ float s2[2];
    const int m = blockIdx.x * 64 + threadIdx.x;
    const int lane = threadIdx.x & 31;
    const int warp = threadIdx.x >> 5;
    float ssq = 0.f, ssk = 0.f, wgd = 0.f;
#pragma unroll
    for (int i = 0; i < 4; i++) {
        ssq += g_ssp[(size_t)i * MTOT + m];
        ssk += g_ssp[(size_t)(4 + i) * MTOT + m];
        wgd += g_wgp[(size_t)i * MTOT + m];
    }
    float invq = 1.f / fmaxf(sqrtf(ssq), L2EPS);
    float invk = 1.f / fmaxf(sqrtf(ssk), L2EPS);
    float qg = invq * wgd;
    g_invq[m] = invq;
    g_invk[m] = invk;
    g_c[m] = invq * qg;
    float s = qg * qg;
#pragma unroll
    for (int o = 16; o > 0; o >>= 1) s += __shfl_xor_sync(0xffffffff, s, o);
    if (lane == 0) s2[warp] = s;
    __syncthreads();
    if (threadIdx.x == 0) g_sspart[blockIdx.x] = s2[0] + s2[1];
}

// ---------------- G partials: Gpart[blk] = sum_m c_m * Qpre_m ----------------
__global__ __launch_bounds__(256) void k_gpart()
{
    __shared__ float sG[8][512];
    const int tid  = threadIdx.x;
    const int lane = tid & 31;
    const int warp = tid >> 5;
    const int m0 = blockIdx.x * 64;

    float Gl[16];
#pragma unroll
    for (int u = 0; u < 16; u++) Gl[u] = 0.f;

    for (int t = warp; t < 64; t += 8) {
        const int m = m0 + t;
        const float cm = g_c[m];
        size_t base = (size_t)m * 512 + lane * 16;
        uint4 a0 = *(const uint4*)(gq_hi + base);
        uint4 a1 = *(const uint4*)(gq_hi + base + 8);
        uint4 b0 = *(const uint4*)(gq_lo + base);
        uint4 b1 = *(const uint4*)(gq_lo + base + 8);
        const __nv_bfloat16* h0 = (const __nv_bfloat16*)&a0;
        const __nv_bfloat16* h1 = (const __nv_bfloat16*)&a1;
        const __nv_bfloat16* l0 = (const __nv_bfloat16*)&b0;
        const __nv_bfloat16* l1 = (const __nv_bfloat16*)&b1;
#pragma unroll
        for (int j = 0; j < 8; j++) {
            Gl[j]     += cm * (__bfloat162float(h0[j]) + __bfloat162float(l0[j]));
            Gl[8 + j] += cm * (__bfloat162float(h1[j]) + __bfloat162float(l1[j]));
        }
    }
#pragma unroll
    for (int j = 0; j < 16; j++) sG[warp][lane * 16 + j] = Gl[j];
    __syncthreads();
    for (int j = tid; j < 512; j += 256) {
        float s = 0.f;
#pragma unroll
        for (int w2 = 0; w2 < 8; w2++) s += sG[w2][j];
        g_Gpart[blockIdx.x * 512 + j] = s;
    }
}

// ---------------- per-batch finalize: G, dyn assembly, softmax ---------------
__global__ __launch_bounds__(256) void k_finalize(const float* __restrict__ bd2)
{
    __shared__ float red[256];
    const int b   = blockIdx.x;
    const int tid = threadIdx.x;
    const float bd2v = bd2[0];

    if (tid == 0) {
        float s = 0.f;
        for (int i = 0; i < 49; i++) s += g_sspart[b * 49 + i];
        red[0] = s;
    }
    __syncthreads();
    const float SCALE = 0.0625f;      // 256^-0.5
    float denom = fmaxf(SCALE * sqrtf(red[0]), L2EPS);
    float f = SCALE / denom;
    __syncthreads();

    for (int j = tid; j < 512; j += 256) {
        float s = 0.f;
        for (int i = 0; i < 49; i++) s += g_Gpart[(size_t)(b * 49 + i) * 512 + j];
        g_G[b * 512 + j] = f * s;
    }

    float mx = -1e30f;
    for (int n = tid; n < NTOK; n += 256) {
        size_t idx = (size_t)b * NTOK + n;
        float v = g_dynpart[idx] + g_dynpart[(size_t)MTOT + idx]
                + g_dynpart[2 * (size_t)MTOT + idx] + g_dynpart[3 * (size_t)MTOT + idx] + bd2v;
        g_dyn[idx] = v;
        mx = fmaxf(mx, v);
    }
    red[tid] = mx; __syncthreads();
    for (int o = 128; o > 0; o >>= 1) { if (tid < o) red[tid] = fmaxf(red[tid], red[tid + o]); __syncthreads(); }
    mx = red[0]; __syncthreads();

    float se = 0.f;
    for (int n = tid; n < NTOK; n += 256) se += expf(g_dyn[b * NTOK + n] - mx);
    red[tid] = se; __syncthreads();
    for (int o = 128; o > 0; o >>= 1) { if (tid < o) red[tid] += red[tid + o]; __syncthreads(); }
    float inv = 1.f / red[0];
    for (int n = tid; n < NTOK; n += 256)
        g_w[b * NTOK + n] = expf(g_dyn[b * NTOK + n] - mx) * inv;
}

// -----------------------------------------------------------------------------
extern "C" void kernel_launch(void* const* d_in, const int* in_sizes, int n_in,
                              void* d_out, int out_size)
{
    const float* x   = (const float*)d_in[0];
    const float* wq  = (const float*)d_in[1];
    const float* bq  = (const float*)d_in[2];
    const float* wk  = (const float*)d_in[3];
    const float* bk  = (const float*)d_in[4];
    const float* w_g = (const float*)d_in[5];
    const float* wd1 = (const float*)d_in[6];
    const float* bd1 = (const float*)d_in[7];
    const float* wd2 = (const float*)d_in[8];
    const float* bd2 = (const float*)d_in[9];
    const float* wf  = (const float*)d_in[10];
    const float* bf  = (const float*)d_in[11];
    float* out = (float*)d_out;

    cudaFuncSetAttribute(k_gemm_mma<0>, cudaFuncAttributeMaxDynamicSharedMemorySize, SMEM_SZ);
    cudaFuncSetAttribute(k_gemm_mma<1>, cudaFuncAttributeMaxDynamicSharedMemorySize, SMEM_SZ);
    cudaFuncSetAttribute(k_gemm_mma<2>, cudaFuncAttributeMaxDynamicSharedMemorySize, SMEM_SZ_OUT);

    k_prep_w<<<dim3(16, 16, 4), dim3(32, 8)>>>(wq, wk, wd1, wf);
    k_prep_x<<<dim3(98, 16, 16), dim3(32, 8)>>>(x);
    k_gemm_mma<0><<<dim3(8, MTOT / 128), 256, SMEM_SZ>>>(bq, bk, w_g, nullptr);
    k_scalar<<<NBLK64, 64>>>();
    k_gpart<<<NBLK64, 256>>>();
    k_gemm_mma<1><<<dim3(4, MTOT / 128), 256, SMEM_SZ>>>(bd1, wd2, nullptr, nullptr);
    k_finalize<<<BATCH, 256>>>(bd2);
    k_gemm_mma<2><<<dim3(2, MTOT / 128), 256, SMEM_SZ_OUT>>>(bf, nullptr, nullptr, out);
}